// round 13
// baseline (speedup 1.0000x reference)
#include <cuda_runtime.h>

// Fixed problem shapes (SpanRepresentation_32487132627590)
#define BATCH   4
#define SLEN    2048
#define DIM     768
#define DIM4    (DIM / 4)               // 192
#define NSPAN   4096
#define NROWS   (BATCH * NSPAN)         // 16384
#define CHUNK   64
#define NCHUNK  (SLEN / CHUNK)          // 32
#define NCBLK   (BATCH * NCHUNK)        // 128
#define OUTW    2364
#define OFF_MEAN 0
#define OFF_XS0  768
#define OFF_P0   1536
#define OFF_XS1  1556
#define OFF_P1   2324
#define OFF_W    2344

// exclusive prefix sums cs[b, s, d], s in [0, SLEN]  (~25.2 MB)
__device__ float g_cs[(size_t)BATCH * (SLEN + 1) * DIM];
// per-chunk sums and their exclusive prefixes
__device__ float g_chunk[(size_t)BATCH * NCHUNK * DIM];
__device__ float g_pref [(size_t)BATCH * NCHUNK * DIM];

// ---------------------------------------------------------------------------
// K1: per-chunk partial sums (proven config).  grid = 128, block = 768
// Triggers early so the PDL chain cascades.
// ---------------------------------------------------------------------------
__global__ __launch_bounds__(DIM)
void chunksum_kernel(const float* __restrict__ x) {
    cudaTriggerProgrammaticLaunchCompletion();
    const int d  = threadIdx.x;
    const int bc = blockIdx.x;
    const float* p = x + (size_t)bc * CHUNK * DIM + d;

    float a0 = 0.f, a1 = 0.f, a2 = 0.f, a3 = 0.f;
    #pragma unroll
    for (int i = 0; i < CHUNK; i += 4) {
        a0 += p[(size_t)(i + 0) * DIM];
        a1 += p[(size_t)(i + 1) * DIM];
        a2 += p[(size_t)(i + 2) * DIM];
        a3 += p[(size_t)(i + 3) * DIM];
    }
    g_chunk[(size_t)bc * DIM + d] = (a0 + a1) + (a2 + a3);
}

// ---------------------------------------------------------------------------
// K2: exclusive scan of 32 chunk sums per (b,d).  grid = 4, block = 768
// ---------------------------------------------------------------------------
__global__ __launch_bounds__(DIM)
void chunk_prefix_kernel() {
    cudaTriggerProgrammaticLaunchCompletion();   // let scan launch early
    cudaGridDependencySynchronize();             // wait: chunksum complete
    const int d = threadIdx.x;
    const int b = blockIdx.x;
    const float* ch = g_chunk + (size_t)b * NCHUNK * DIM + d;
    float*       pf = g_pref  + (size_t)b * NCHUNK * DIM + d;

    float v[NCHUNK];
    #pragma unroll
    for (int c = 0; c < NCHUNK; c++) v[c] = ch[(size_t)c * DIM];

    float run = 0.f;
    #pragma unroll
    for (int c = 0; c < NCHUNK; c++) {
        pf[(size_t)c * DIM] = run;
        run += v[c];
    }
}

// ---------------------------------------------------------------------------
// K3: pure streaming scan -> cs.  grid = 128, block = 768
// ---------------------------------------------------------------------------
__global__ __launch_bounds__(DIM)
void scan_write_kernel(const float* __restrict__ x) {
    cudaTriggerProgrammaticLaunchCompletion();   // let span_rest launch early
    cudaGridDependencySynchronize();             // wait: prefix complete
    const int d  = threadIdx.x;
    const int bc = blockIdx.x;
    const int b  = bc / NCHUNK;
    const int c  = bc % NCHUNK;

    float run = g_pref[(size_t)bc * DIM + d];

    const float* p = x    + ((size_t)b * SLEN       + (size_t)c * CHUNK) * DIM + d;
    float*       q = g_cs + ((size_t)b * (SLEN + 1) + (size_t)c * CHUNK) * DIM + d;

    #pragma unroll 4
    for (int i = 0; i < CHUNK; i++) {
        q[(size_t)i * DIM] = run;
        run += p[(size_t)i * DIM];
    }
    if (c == NCHUNK - 1) q[(size_t)CHUNK * DIM] = run;   // cs[SLEN]
}

// ---------------------------------------------------------------------------
// K4: span_rest — xs0/pos0/xs1/pos1/width.  grid = 16384, block = 192
// NO dependency on cs: launched with PDL so it runs concurrently with K1-K3.
// ---------------------------------------------------------------------------
__global__ __launch_bounds__(DIM4)
void span_rest_kernel(const float* __restrict__ x,
                      const int* __restrict__ spans,
                      const int* __restrict__ pt_labels,
                      const float* __restrict__ wtab,
                      const float* __restrict__ ptab,
                      float* __restrict__ out) {
    const int bn = blockIdx.x;
    const int b  = bn >> 12;
    const int n  = bn & (NSPAN - 1);
    const int t  = threadIdx.x;

    const int i0 = spans[2 * n + 0];
    const int i1 = spans[2 * n + 1];
    const int width = i1 - i0 + 1;

    const int bins[16] = {0,1,2,3,4,5,7,8,9,10,15,16,31,32,63,64};
    int em = 0;
    #pragma unroll
    for (int i = 1; i < 16; i++) em = (width >= bins[i]) ? i : em;

    const int l0 = pt_labels[i0];
    const int l1 = pt_labels[i1];

    const float4 v0 = ((const float4*)(x + ((size_t)b * SLEN + i0) * DIM))[t];
    const float4 v1 = ((const float4*)(x + ((size_t)b * SLEN + i1) * DIM))[t];
    float* orow = out + (size_t)bn * OUTW;

    ((float4*)(orow + OFF_XS0))[t] = v0;
    ((float4*)(orow + OFF_XS1))[t] = v1;

    if (t < 5) {
        ((float4*)(orow + OFF_P0))[t] = ((const float4*)(ptab + l0 * 20))[t];
        ((float4*)(orow + OFF_P1))[t] = ((const float4*)(ptab + l1 * 20))[t];
        ((float4*)(orow + OFF_W ))[t] = ((const float4*)(wtab + em * 20))[t];
    }
}

// ---------------------------------------------------------------------------
// K5: span_mean — needs cs.  grid = 16384, block = 192.
// Launched with FULL dependency on K4; K3 (scan) is provably complete by then
// (scan's blocks are resident before K4's flood and finish far earlier).
// ---------------------------------------------------------------------------
__global__ __launch_bounds__(DIM4)
void span_mean_kernel(const int* __restrict__ spans,
                      float* __restrict__ out) {
    const int bn = blockIdx.x;
    const int b  = bn >> 12;
    const int n  = bn & (NSPAN - 1);
    const int t  = threadIdx.x;

    const int i0 = spans[2 * n + 0];
    const int i1 = spans[2 * n + 1];
    const float inv_w = 1.0f / (float)(i1 - i0 + 1);

    const float4 a  = ((const float4*)(g_cs + ((size_t)b * (SLEN + 1) + i0    ) * DIM))[t];
    const float4 bb = ((const float4*)(g_cs + ((size_t)b * (SLEN + 1) + i1 + 1) * DIM))[t];

    float4 m;
    m.x = (bb.x - a.x) * inv_w;
    m.y = (bb.y - a.y) * inv_w;
    m.z = (bb.z - a.z) * inv_w;
    m.w = (bb.w - a.w) * inv_w;
    ((float4*)(out + (size_t)bn * OUTW + OFF_MEAN))[t] = m;
}

// ---------------------------------------------------------------------------
extern "C" void kernel_launch(void* const* d_in, const int* in_sizes, int n_in,
                              void* d_out, int out_size) {
    const float* x      = (const float*)d_in[0];
    const int*   spans  = (const int*)d_in[1];
    const int*   labels = (const int*)d_in[2];
    const float* wtab   = (const float*)d_in[3];
    const float* ptab   = (const float*)d_in[4];
    float*       out    = (float*)d_out;

    cudaLaunchAttribute pdl[1];
    pdl[0].id = cudaLaunchAttributeProgrammaticStreamSerialization;
    pdl[0].val.programmaticStreamSerializationAllowed = 1;

    // K1: normal launch
    chunksum_kernel<<<NCBLK, DIM>>>(x);

    // K2: PDL (launches when K1 triggers; griddepsync guards data)
    {
        cudaLaunchConfig_t cfg = {};
        cfg.gridDim = dim3(BATCH); cfg.blockDim = dim3(DIM);
        cfg.stream = 0; cfg.attrs = pdl; cfg.numAttrs = 1;
        cudaLaunchKernelEx(&cfg, chunk_prefix_kernel);
    }
    // K3: PDL
    {
        cudaLaunchConfig_t cfg = {};
        cfg.gridDim = dim3(NCBLK); cfg.blockDim = dim3(DIM);
        cfg.stream = 0; cfg.attrs = pdl; cfg.numAttrs = 1;
        cudaLaunchKernelEx(&cfg, scan_write_kernel, x);
    }
    // K4: PDL, no data dependency — overlaps the whole cumsum chain
    {
        cudaLaunchConfig_t cfg = {};
        cfg.gridDim = dim3(NROWS); cfg.blockDim = dim3(DIM4);
        cfg.stream = 0; cfg.attrs = pdl; cfg.numAttrs = 1;
        cudaLaunchKernelEx(&cfg, span_rest_kernel, x, spans, labels, wtab, ptab, out);
    }
    // K5: normal launch — full completion dependency on K4
    span_mean_kernel<<<NROWS, DIM4>>>(spans, out);
}

// round 14
// speedup vs baseline: 1.0604x; 1.0604x over previous
#include <cuda_runtime.h>

// Fixed problem shapes (SpanRepresentation_32487132627590)
#define BATCH   4
#define SLEN    2048
#define DIM     768
#define DIM4    (DIM / 4)               // 192
#define NSPAN   4096
#define NROWS   (BATCH * NSPAN)         // 16384
#define CHUNK   32
#define NCHUNK  (SLEN / CHUNK)          // 64
#define NCBLK   (BATCH * NCHUNK)        // 256
#define OUTW    2364
#define OFF_MEAN 0
#define OFF_XS0  768
#define OFF_P0   1536
#define OFF_XS1  1556
#define OFF_P1   2324
#define OFF_W    2344

// exclusive prefix sums cs[b, s, d], s in [0, SLEN]  (~25.2 MB)
__device__ float g_cs[(size_t)BATCH * (SLEN + 1) * DIM];
// per-chunk sums and their exclusive prefixes
__device__ float g_chunk[(size_t)BATCH * NCHUNK * DIM];
__device__ float g_pref [(size_t)BATCH * NCHUNK * DIM];

// ---------------------------------------------------------------------------
// K1: per-chunk partial sums.  grid = 256 (covers all SMs), block = 768,
// 8 independent accumulators -> 8 outstanding loads per thread (MLP 8).
// ---------------------------------------------------------------------------
__global__ __launch_bounds__(DIM)
void chunksum_kernel(const float* __restrict__ x) {
    const int d  = threadIdx.x;
    const int bc = blockIdx.x;
    const float* p = x + (size_t)bc * CHUNK * DIM + d;

    float a0 = 0.f, a1 = 0.f, a2 = 0.f, a3 = 0.f;
    float a4 = 0.f, a5 = 0.f, a6 = 0.f, a7 = 0.f;
    #pragma unroll
    for (int i = 0; i < CHUNK; i += 8) {
        a0 += p[(size_t)(i + 0) * DIM];
        a1 += p[(size_t)(i + 1) * DIM];
        a2 += p[(size_t)(i + 2) * DIM];
        a3 += p[(size_t)(i + 3) * DIM];
        a4 += p[(size_t)(i + 4) * DIM];
        a5 += p[(size_t)(i + 5) * DIM];
        a6 += p[(size_t)(i + 6) * DIM];
        a7 += p[(size_t)(i + 7) * DIM];
    }
    g_chunk[(size_t)bc * DIM + d] = ((a0 + a1) + (a2 + a3)) + ((a4 + a5) + (a6 + a7));
}

// ---------------------------------------------------------------------------
// K2: exclusive scan of the 64 chunk sums per (b, d).  grid = 4, block = 768
// Preload all values (independent loads), then serial adds in registers.
// ---------------------------------------------------------------------------
__global__ __launch_bounds__(DIM)
void chunk_prefix_kernel() {
    const int d = threadIdx.x;
    const int b = blockIdx.x;
    const float* ch = g_chunk + (size_t)b * NCHUNK * DIM + d;
    float*       pf = g_pref  + (size_t)b * NCHUNK * DIM + d;

    float v[NCHUNK];
    #pragma unroll
    for (int c = 0; c < NCHUNK; c++) v[c] = ch[(size_t)c * DIM];

    float run = 0.f;
    #pragma unroll
    for (int c = 0; c < NCHUNK; c++) {
        pf[(size_t)c * DIM] = run;
        run += v[c];
    }
}

// ---------------------------------------------------------------------------
// K3: pure streaming scan -> cs.  grid = 256, block = 768
// ---------------------------------------------------------------------------
__global__ __launch_bounds__(DIM)
void scan_write_kernel(const float* __restrict__ x) {
    const int d  = threadIdx.x;
    const int bc = blockIdx.x;
    const int b  = bc / NCHUNK;
    const int c  = bc % NCHUNK;

    float run = g_pref[(size_t)bc * DIM + d];   // exclusive chunk prefix

    const float* p = x    + ((size_t)b * SLEN       + (size_t)c * CHUNK) * DIM + d;
    float*       q = g_cs + ((size_t)b * (SLEN + 1) + (size_t)c * CHUNK) * DIM + d;

    #pragma unroll 4
    for (int i = 0; i < CHUNK; i++) {
        q[(size_t)i * DIM] = run;
        run += p[(size_t)i * DIM];
    }
    if (c == NCHUNK - 1) q[(size_t)CHUNK * DIM] = run;   // cs[SLEN]
}

// ---------------------------------------------------------------------------
// K4 (proven, untouched): one block per output row.  grid = 16384, block=192
// ---------------------------------------------------------------------------
__global__ __launch_bounds__(DIM4)
void span_kernel(const float* __restrict__ x,
                 const int* __restrict__ spans,
                 const int* __restrict__ pt_labels,
                 const float* __restrict__ wtab,
                 const float* __restrict__ ptab,
                 float* __restrict__ out) {
    const int bn = blockIdx.x;
    const int b  = bn >> 12;
    const int n  = bn & (NSPAN - 1);
    const int t  = threadIdx.x;

    const int i0 = spans[2 * n + 0];
    const int i1 = spans[2 * n + 1];
    const int width = i1 - i0 + 1;

    const int bins[16] = {0,1,2,3,4,5,7,8,9,10,15,16,31,32,63,64};
    int em = 0;
    #pragma unroll
    for (int i = 1; i < 16; i++) em = (width >= bins[i]) ? i : em;

    const int l0 = pt_labels[i0];
    const int l1 = pt_labels[i1];
    const float inv_w = 1.0f / (float)width;

    const float4 a  = ((const float4*)(g_cs + ((size_t)b * (SLEN + 1) + i0    ) * DIM))[t];
    const float4 bb = ((const float4*)(g_cs + ((size_t)b * (SLEN + 1) + i1 + 1) * DIM))[t];
    const float4 v0 = ((const float4*)(x    + ((size_t)b * SLEN + i0) * DIM))[t];
    const float4 v1 = ((const float4*)(x    + ((size_t)b * SLEN + i1) * DIM))[t];
    float* orow = out + (size_t)bn * OUTW;

    float4 m;
    m.x = (bb.x - a.x) * inv_w;
    m.y = (bb.y - a.y) * inv_w;
    m.z = (bb.z - a.z) * inv_w;
    m.w = (bb.w - a.w) * inv_w;

    ((float4*)(orow + OFF_MEAN))[t] = m;
    ((float4*)(orow + OFF_XS0 ))[t] = v0;
    ((float4*)(orow + OFF_XS1 ))[t] = v1;

    if (t < 5) {
        ((float4*)(orow + OFF_P0))[t] = ((const float4*)(ptab + l0 * 20))[t];
        ((float4*)(orow + OFF_P1))[t] = ((const float4*)(ptab + l1 * 20))[t];
        ((float4*)(orow + OFF_W ))[t] = ((const float4*)(wtab + em * 20))[t];
    }
}

// ---------------------------------------------------------------------------
extern "C" void kernel_launch(void* const* d_in, const int* in_sizes, int n_in,
                              void* d_out, int out_size) {
    const float* x      = (const float*)d_in[0];
    const int*   spans  = (const int*)d_in[1];
    const int*   labels = (const int*)d_in[2];
    const float* wtab   = (const float*)d_in[3];
    const float* ptab   = (const float*)d_in[4];
    float*       out    = (float*)d_out;

    chunksum_kernel    <<<NCBLK, DIM>>>(x);
    chunk_prefix_kernel<<<BATCH, DIM>>>();
    scan_write_kernel  <<<NCBLK, DIM>>>(x);
    span_kernel        <<<NROWS, DIM4>>>(x, spans, labels, wtab, ptab, out);
}

// round 15
// speedup vs baseline: 1.1574x; 1.0915x over previous
#include <cuda_runtime.h>

// Fixed problem shapes (SpanRepresentation_32487132627590)
#define BATCH   4
#define SLEN    2048
#define DIM     768
#define DIM4    (DIM / 4)               // 192
#define NSPAN   4096
#define NROWS   (BATCH * NSPAN)         // 16384
#define CHUNK   64
#define NCHUNK  (SLEN / CHUNK)          // 32
#define NCBLK   (BATCH * NCHUNK)        // 128
#define OUTW    2364
#define OFF_MEAN 0
#define OFF_XS0  768
#define OFF_P0   1536
#define OFF_XS1  1556
#define OFF_P1   2324
#define OFF_W    2344

// exclusive prefix sums cs[b, s, d], s in [0, SLEN]  (~25.2 MB)
__device__ float g_cs[(size_t)BATCH * (SLEN + 1) * DIM];
// per-chunk sums
__device__ float g_chunk[(size_t)BATCH * NCHUNK * DIM];

// ---------------------------------------------------------------------------
// K1: per-chunk partial sums.  grid = 128, block = 768.
// 16 independent accumulators -> 16 outstanding DRAM loads per thread.
// ---------------------------------------------------------------------------
__global__ __launch_bounds__(DIM)
void chunksum_kernel(const float* __restrict__ x) {
    const int d  = threadIdx.x;
    const int bc = blockIdx.x;
    const float* p = x + (size_t)bc * CHUNK * DIM + d;

    float a[16];
    #pragma unroll
    for (int k = 0; k < 16; k++) a[k] = p[(size_t)k * DIM];
    #pragma unroll
    for (int i = 16; i < CHUNK; i += 16) {
        #pragma unroll
        for (int k = 0; k < 16; k++) a[k] += p[(size_t)(i + k) * DIM];
    }
    // pairwise reduce
    #pragma unroll
    for (int s = 8; s > 0; s >>= 1) {
        #pragma unroll
        for (int k = 0; k < s; k++) a[k] += a[k + s];
    }
    g_chunk[(size_t)bc * DIM + d] = a[0];
}

// ---------------------------------------------------------------------------
// K2 (R11-proven): scan -> cs with inline chunk-prefix (unrolled, predicated,
// 32 independent L2-hot loads).  grid = 128, block = 768
// ---------------------------------------------------------------------------
__global__ __launch_bounds__(DIM)
void scan_write_kernel(const float* __restrict__ x) {
    const int d  = threadIdx.x;
    const int bc = blockIdx.x;
    const int b  = bc / NCHUNK;
    const int c  = bc % NCHUNK;

    // exclusive prefix of chunk sums (g_chunk is tiny and L2-resident)
    const float* ch = g_chunk + (size_t)b * NCHUNK * DIM + d;
    float run = 0.f;
    #pragma unroll
    for (int cc = 0; cc < NCHUNK; cc++) {
        float v = (cc < c) ? ch[(size_t)cc * DIM] : 0.f;
        run += v;
    }

    const float* p = x    + ((size_t)b * SLEN       + (size_t)c * CHUNK) * DIM + d;
    float*       q = g_cs + ((size_t)b * (SLEN + 1) + (size_t)c * CHUNK) * DIM + d;

    #pragma unroll 4
    for (int i = 0; i < CHUNK; i++) {
        q[(size_t)i * DIM] = run;
        run += p[(size_t)i * DIM];
    }
    if (c == NCHUNK - 1) q[(size_t)CHUNK * DIM] = run;   // cs[SLEN]
}

// ---------------------------------------------------------------------------
// K3 (proven, untouched): one block per output row.  grid = 16384, block=192
// ---------------------------------------------------------------------------
__global__ __launch_bounds__(DIM4)
void span_kernel(const float* __restrict__ x,
                 const int* __restrict__ spans,
                 const int* __restrict__ pt_labels,
                 const float* __restrict__ wtab,
                 const float* __restrict__ ptab,
                 float* __restrict__ out) {
    const int bn = blockIdx.x;
    const int b  = bn >> 12;
    const int n  = bn & (NSPAN - 1);
    const int t  = threadIdx.x;

    const int i0 = spans[2 * n + 0];
    const int i1 = spans[2 * n + 1];
    const int width = i1 - i0 + 1;

    const int bins[16] = {0,1,2,3,4,5,7,8,9,10,15,16,31,32,63,64};
    int em = 0;
    #pragma unroll
    for (int i = 1; i < 16; i++) em = (width >= bins[i]) ? i : em;

    const int l0 = pt_labels[i0];
    const int l1 = pt_labels[i1];
    const float inv_w = 1.0f / (float)width;

    const float4 a  = ((const float4*)(g_cs + ((size_t)b * (SLEN + 1) + i0    ) * DIM))[t];
    const float4 bb = ((const float4*)(g_cs + ((size_t)b * (SLEN + 1) + i1 + 1) * DIM))[t];
    const float4 v0 = ((const float4*)(x    + ((size_t)b * SLEN + i0) * DIM))[t];
    const float4 v1 = ((const float4*)(x    + ((size_t)b * SLEN + i1) * DIM))[t];
    float* orow = out + (size_t)bn * OUTW;

    float4 m;
    m.x = (bb.x - a.x) * inv_w;
    m.y = (bb.y - a.y) * inv_w;
    m.z = (bb.z - a.z) * inv_w;
    m.w = (bb.w - a.w) * inv_w;

    ((float4*)(orow + OFF_MEAN))[t] = m;
    ((float4*)(orow + OFF_XS0 ))[t] = v0;
    ((float4*)(orow + OFF_XS1 ))[t] = v1;

    if (t < 5) {
        ((float4*)(orow + OFF_P0))[t] = ((const float4*)(ptab + l0 * 20))[t];
        ((float4*)(orow + OFF_P1))[t] = ((const float4*)(ptab + l1 * 20))[t];
        ((float4*)(orow + OFF_W ))[t] = ((const float4*)(wtab + em * 20))[t];
    }
}

// ---------------------------------------------------------------------------
extern "C" void kernel_launch(void* const* d_in, const int* in_sizes, int n_in,
                              void* d_out, int out_size) {
    const float* x      = (const float*)d_in[0];
    const int*   spans  = (const int*)d_in[1];
    const int*   labels = (const int*)d_in[2];
    const float* wtab   = (const float*)d_in[3];
    const float* ptab   = (const float*)d_in[4];
    float*       out    = (float*)d_out;

    chunksum_kernel  <<<NCBLK, DIM>>>(x);
    scan_write_kernel<<<NCBLK, DIM>>>(x);
    span_kernel      <<<NROWS, DIM4>>>(x, spans, labels, wtab, ptab, out);
}